// round 8
// baseline (speedup 1.0000x reference)
#include <cuda_runtime.h>
#include <math_constants.h>
#include <cstdint>
#include <cstddef>

// Problem constants: B=8, L=1024, H=1024, NH=16, HD=64, scale = 1/8
#define B_SZ   8
#define L_SZ   1024
#define H_SZ   1024
#define NH_SZ  16
#define HD_SZ  64
#define ML     8192            // B*L
#define QKVN   3072            // 3*H

// Scratch (device globals — no allocation allowed)
__device__ float g_qkv[(size_t)ML * QKVN];   // [B*L, 3H]
__device__ float g_o[(size_t)ML * H_SZ];     // [B*L, H]

// ---------------------------------------------------------------------------
// GEMM (NT): C[M,N] = A[M,K] * B[N,K]^T (+ bias[n]), all row-major, K contig.
// 128x128 tile, BK=8, 256 threads, 8x8 per thread in four 4x4 quadrants.
// Double-buffered smem: one __syncthreads per K-step, global prefetch into
// registers overlaps the FFMA block.
// ---------------------------------------------------------------------------
__global__ __launch_bounds__(256) void gemm_nt_128x128(
    const float* __restrict__ A, const float* __restrict__ Bm,
    const float* __restrict__ bias, float* __restrict__ C,
    int M, int N, int K)
{
    __shared__ float As[2][8][132];
    __shared__ float Bs[2][8][132];
    const int t  = threadIdx.x;
    const int m0 = blockIdx.y * 128;
    const int n0 = blockIdx.x * 128;
    const int lr = t >> 1;           // 0..127: tile row (A) / tile row (B)
    const int lk = (t & 1) * 4;      // 0 or 4: k sub-offset
    const float* Ap = A + (size_t)(m0 + lr) * K + lk;
    const float* Bp = Bm + (size_t)(n0 + lr) * K + lk;
    const int ty4 = (t >> 4) * 4;    // 0..60
    const int tx4 = (t & 15) * 4;    // 0..60

    float acc[8][8];
#pragma unroll
    for (int i = 0; i < 8; i++)
#pragma unroll
        for (int j = 0; j < 8; j++) acc[i][j] = 0.f;

    // Prologue: load k0 = 0 into buffer 0
    {
        float4 av = *(const float4*)(Ap);
        float4 bv = *(const float4*)(Bp);
        As[0][lk + 0][lr] = av.x; As[0][lk + 1][lr] = av.y;
        As[0][lk + 2][lr] = av.z; As[0][lk + 3][lr] = av.w;
        Bs[0][lk + 0][lr] = bv.x; Bs[0][lk + 1][lr] = bv.y;
        Bs[0][lk + 2][lr] = bv.z; Bs[0][lk + 3][lr] = bv.w;
    }
    __syncthreads();

    int buf = 0;
    for (int k0 = 8; k0 <= K; k0 += 8) {
        // Prefetch next tile (overlaps with compute below)
        float4 av2, bv2;
        const bool more = (k0 < K);
        if (more) {
            av2 = *(const float4*)(Ap + k0);
            bv2 = *(const float4*)(Bp + k0);
        }

        // Compute on current buffer
#pragma unroll
        for (int k = 0; k < 8; k++) {
            float a[8], b[8];
            {
                float4 v = *(const float4*)&As[buf][k][ty4];
                a[0] = v.x; a[1] = v.y; a[2] = v.z; a[3] = v.w;
                v = *(const float4*)&As[buf][k][64 + ty4];
                a[4] = v.x; a[5] = v.y; a[6] = v.z; a[7] = v.w;
                v = *(const float4*)&Bs[buf][k][tx4];
                b[0] = v.x; b[1] = v.y; b[2] = v.z; b[3] = v.w;
                v = *(const float4*)&Bs[buf][k][64 + tx4];
                b[4] = v.x; b[5] = v.y; b[6] = v.z; b[7] = v.w;
            }
#pragma unroll
            for (int i = 0; i < 8; i++)
#pragma unroll
                for (int j = 0; j < 8; j++)
                    acc[i][j] = fmaf(a[i], b[j], acc[i][j]);
        }

        // Store prefetched tile into the other buffer.
        // Safe with a single barrier: every thread finished reading `buf`
        // (program order above) and all reads of `buf^1` from the previous
        // iteration were fenced by the previous __syncthreads.
        if (more) {
            const int nb = buf ^ 1;
            As[nb][lk + 0][lr] = av2.x; As[nb][lk + 1][lr] = av2.y;
            As[nb][lk + 2][lr] = av2.z; As[nb][lk + 3][lr] = av2.w;
            Bs[nb][lk + 0][lr] = bv2.x; Bs[nb][lk + 1][lr] = bv2.y;
            Bs[nb][lk + 2][lr] = bv2.z; Bs[nb][lk + 3][lr] = bv2.w;
            __syncthreads();
            buf = nb;
        }
    }

    float bb[8];
    if (bias != nullptr) {
#pragma unroll
        for (int j = 0; j < 4; j++) {
            bb[j]     = bias[n0 + tx4 + j];
            bb[4 + j] = bias[n0 + 64 + tx4 + j];
        }
    } else {
#pragma unroll
        for (int j = 0; j < 8; j++) bb[j] = 0.f;
    }

#pragma unroll
    for (int i = 0; i < 8; i++) {
        int row = m0 + ((i < 4) ? (ty4 + i) : (64 + ty4 + (i - 4)));
        float4 v0 = make_float4(acc[i][0] + bb[0], acc[i][1] + bb[1],
                                acc[i][2] + bb[2], acc[i][3] + bb[3]);
        float4 v1 = make_float4(acc[i][4] + bb[4], acc[i][5] + bb[5],
                                acc[i][6] + bb[6], acc[i][7] + bb[7]);
        *(float4*)&C[(size_t)row * N + n0 + tx4]      = v0;
        *(float4*)&C[(size_t)row * N + n0 + 64 + tx4] = v1;
    }
}

// ---------------------------------------------------------------------------
// Flash attention: one CTA = (64 q-rows) x (one b,h). Streams 16 k-tiles of 64.
// Q,K stored k-major (transposed) in smem for float4 operand loads.
// Online softmax with running (m, l); O accumulated in registers (4x4/thread).
// Writes o in [B, L, H] layout with H index = h*64 + d (ready for out-proj).
// ---------------------------------------------------------------------------
#define ATTN_SMEM_FLOATS (64*68 + 64*68 + 64*64 + 64*65 + 3*64)
#define ATTN_SMEM_BYTES  (ATTN_SMEM_FLOATS * 4)

__global__ __launch_bounds__(256) void attn_flash_kernel(
    const float* __restrict__ qkv, float* __restrict__ o)
{
    extern __shared__ float sm[];
    float* Qt    = sm;                 // [64 d][68]  Qt[d*68 + x], pre-scaled
    float* Kt    = Qt + 64 * 68;       // [64 d][68]  Kt[d*68 + y]
    float* Vs    = Kt + 64 * 68;       // [64 y][64]  Vs[y*64 + d]
    float* Ss    = Vs + 64 * 64;       // [64 r][65]  scores -> probs
    float* row_m = Ss + 64 * 65;       // [64]
    float* row_l = row_m + 64;         // [64]
    float* row_c = row_l + 64;         // [64] correction factor

    const int t  = threadIdx.x;
    const int qb = blockIdx.x;         // 0..15 q-tile
    const int bh = blockIdx.y;         // 0..127
    const int b  = bh >> 4;
    const int h  = bh & 15;
    const int x0 = qb * 64;

    const float* qbase = qkv + ((size_t)(b * L_SZ + x0)) * QKVN + h * HD_SZ;
    const float* kbase = qkv + (size_t)b * L_SZ * QKVN + H_SZ + h * HD_SZ;
    const float* vbase = kbase + H_SZ;
    const float scale = 0.125f;        // 1/sqrt(64)

    // Load Q tile (transposed, pre-scaled). Coalesced over d.
#pragma unroll
    for (int i = 0; i < 16; i++) {
        int idx = t + 256 * i;
        int x = idx >> 6, d = idx & 63;
        Qt[d * 68 + x] = qbase[(size_t)x * QKVN + d] * scale;
    }
    if (t < 64) { row_m[t] = -CUDART_INF_F; row_l[t] = 0.f; }

    const int r0 = (t >> 4) * 4;       // q-row group
    const int c0 = (t & 15) * 4;       // k-col / out-col group
    float acc[4][4];
#pragma unroll
    for (int i = 0; i < 4; i++)
#pragma unroll
        for (int j = 0; j < 4; j++) acc[i][j] = 0.f;

    for (int kt = 0; kt < 16; kt++) {
        const float* kp = kbase + (size_t)kt * 64 * QKVN;
        const float* vp = vbase + (size_t)kt * 64 * QKVN;
        __syncthreads();   // previous PV reads of Kt/Vs/Ss done (also covers Q init)
#pragma unroll
        for (int i = 0; i < 16; i++) {
            int idx = t + 256 * i;
            int y = idx >> 6, d = idx & 63;
            Kt[d * 68 + y] = kp[(size_t)y * QKVN + d];
            Vs[y * 64 + d] = vp[(size_t)y * QKVN + d];
        }
        __syncthreads();

        // S = (scaled Q) K^T : 4x4 per thread
        float s[4][4];
#pragma unroll
        for (int i = 0; i < 4; i++)
#pragma unroll
            for (int j = 0; j < 4; j++) s[i][j] = 0.f;
#pragma unroll 16
        for (int d = 0; d < 64; d++) {
            float4 qa = *(const float4*)&Qt[d * 68 + r0];
            float4 kb = *(const float4*)&Kt[d * 68 + c0];
            s[0][0] = fmaf(qa.x, kb.x, s[0][0]); s[0][1] = fmaf(qa.x, kb.y, s[0][1]);
            s[0][2] = fmaf(qa.x, kb.z, s[0][2]); s[0][3] = fmaf(qa.x, kb.w, s[0][3]);
            s[1][0] = fmaf(qa.y, kb.x, s[1][0]); s[1][1] = fmaf(qa.y, kb.y, s[1][1]);
            s[1][2] = fmaf(qa.y, kb.z, s[1][2]); s[1][3] = fmaf(qa.y, kb.w, s[1][3]);
            s[2][0] = fmaf(qa.z, kb.x, s[2][0]); s[2][1] = fmaf(qa.z, kb.y, s[2][1]);
            s[2][2] = fmaf(qa.z, kb.z, s[2][2]); s[2][3] = fmaf(qa.z, kb.w, s[2][3]);
            s[3][0] = fmaf(qa.w, kb.x, s[3][0]); s[3][1] = fmaf(qa.w, kb.y, s[3][1]);
            s[3][2] = fmaf(qa.w, kb.z, s[3][2]); s[3][3] = fmaf(qa.w, kb.w, s[3][3]);
        }
#pragma unroll
        for (int i = 0; i < 4; i++)
#pragma unroll
            for (int j = 0; j < 4; j++)
                Ss[(r0 + i) * 65 + c0 + j] = s[i][j];
        __syncthreads();

        // Online softmax: 4 threads per row (r = t/4, seg = t%4)
        {
            const int r = t >> 2, seg = t & 3;
            float mx = -CUDART_INF_F;
#pragma unroll
            for (int j = 0; j < 16; j++)
                mx = fmaxf(mx, Ss[r * 65 + seg * 16 + j]);
            mx = fmaxf(mx, __shfl_xor_sync(0xffffffffu, mx, 1));
            mx = fmaxf(mx, __shfl_xor_sync(0xffffffffu, mx, 2));
            float m_old = row_m[r];
            float m_new = fmaxf(m_old, mx);
            float sum = 0.f;
#pragma unroll
            for (int j = 0; j < 16; j++) {
                float p = __expf(Ss[r * 65 + seg * 16 + j] - m_new);
                Ss[r * 65 + seg * 16 + j] = p;
                sum += p;
            }
            sum += __shfl_xor_sync(0xffffffffu, sum, 1);
            sum += __shfl_xor_sync(0xffffffffu, sum, 2);
            if (seg == 0) {
                row_c[r] = __expf(m_old - m_new);
                row_l[r] = row_l[r] * row_c[r] + sum;
                row_m[r] = m_new;
            }
        }
        __syncthreads();

        // O = O*corr + P V
        float cr[4];
#pragma unroll
        for (int i = 0; i < 4; i++) cr[i] = row_c[r0 + i];
#pragma unroll
        for (int i = 0; i < 4; i++)
#pragma unroll
            for (int j = 0; j < 4; j++) acc[i][j] *= cr[i];
#pragma unroll 16
        for (int y = 0; y < 64; y++) {
            float4 v = *(const float4*)&Vs[y * 64 + c0];
            float p0 = Ss[(r0 + 0) * 65 + y];
            float p1 = Ss[(r0 + 1) * 65 + y];
            float p2 = Ss[(r0 + 2) * 65 + y];
            float p3 = Ss[(r0 + 3) * 65 + y];
            acc[0][0] = fmaf(p0, v.x, acc[0][0]); acc[0][1] = fmaf(p0, v.y, acc[0][1]);
            acc[0][2] = fmaf(p0, v.z, acc[0][2]); acc[0][3] = fmaf(p0, v.w, acc[0][3]);
            acc[1][0] = fmaf(p1, v.x, acc[1][0]); acc[1][1] = fmaf(p1, v.y, acc[1][1]);
            acc[1][2] = fmaf(p1, v.z, acc[1][2]); acc[1][3] = fmaf(p1, v.w, acc[1][3]);
            acc[2][0] = fmaf(p2, v.x, acc[2][0]); acc[2][1] = fmaf(p2, v.y, acc[2][1]);
            acc[2][2] = fmaf(p2, v.z, acc[2][2]); acc[2][3] = fmaf(p2, v.w, acc[2][3]);
            acc[3][0] = fmaf(p3, v.x, acc[3][0]); acc[3][1] = fmaf(p3, v.y, acc[3][1]);
            acc[3][2] = fmaf(p3, v.z, acc[3][2]); acc[3][3] = fmaf(p3, v.w, acc[3][3]);
        }
    }

    // Normalize and store o[b, x, h*64 + c] (row_l writes ordered by the
    // pre-PV __syncthreads of the final iteration)
#pragma unroll
    for (int i = 0; i < 4; i++) {
        float inv = 1.0f / row_l[r0 + i];
        float4 v = make_float4(acc[i][0] * inv, acc[i][1] * inv,
                               acc[i][2] * inv, acc[i][3] * inv);
        *(float4*)&o[((size_t)(b * L_SZ + x0 + r0 + i)) * H_SZ + h * HD_SZ + c0] = v;
    }
}

// ---------------------------------------------------------------------------
extern "C" void kernel_launch(void* const* d_in, const int* in_sizes, int n_in,
                              void* d_out, int out_size)
{
    const float* x     = (const float*)d_in[0];
    const float* w_qkv = (const float*)d_in[1];
    const float* w_out = (const float*)d_in[2];
    const float* b_out = (const float*)d_in[3];
    float* out = (float*)d_out;

    float* qkv = nullptr;
    float* ob  = nullptr;
    cudaGetSymbolAddress((void**)&qkv, g_qkv);
    cudaGetSymbolAddress((void**)&ob,  g_o);

    cudaFuncSetAttribute(attn_flash_kernel,
                         cudaFuncAttributeMaxDynamicSharedMemorySize,
                         ATTN_SMEM_BYTES);

    // 1) QKV projection: g_qkv[8192, 3072] = x[8192,1024] @ w_qkv[3072,1024]^T
    gemm_nt_128x128<<<dim3(QKVN / 128, ML / 128), 256>>>(
        x, w_qkv, nullptr, qkv, ML, QKVN, H_SZ);

    // 2) Attention -> g_o[8192, 1024] (already in [B, L, H] layout)
    attn_flash_kernel<<<dim3(L_SZ / 64, B_SZ * NH_SZ), 256, ATTN_SMEM_BYTES>>>(
        qkv, ob);

    // 3) Output projection + bias: out = g_o @ w_out^T + b_out
    gemm_nt_128x128<<<dim3(H_SZ / 128, ML / 128), 256>>>(
        ob, w_out, b_out, out, ML, H_SZ, H_SZ);
}

// round 11
// speedup vs baseline: 1.4727x; 1.4727x over previous
#include <cuda_runtime.h>
#include <cuda_bf16.h>
#include <math_constants.h>
#include <cstdint>
#include <cstddef>

// Problem constants: B=8, L=1024, H=1024, NH=16, HD=64, scale = 1/8
#define B_SZ   8
#define L_SZ   1024
#define H_SZ   1024
#define NH_SZ  16
#define HD_SZ  64
#define ML     8192            // B*L
#define QKVN   3072            // 3*H

// Scratch (device globals — no allocation allowed)
__device__ float g_qkv[(size_t)ML * QKVN];            // [B*L, 3H] fp32
__device__ float g_o[(size_t)ML * H_SZ];              // [B*L, H]  fp32
// Split-precision bf16 planes (A reused for x then o; B for w_qkv then w_out)
__device__ __nv_bfloat16 g_Ahi[(size_t)ML * H_SZ];
__device__ __nv_bfloat16 g_Alo[(size_t)ML * H_SZ];
__device__ __nv_bfloat16 g_Bhi[(size_t)QKVN * H_SZ];
__device__ __nv_bfloat16 g_Blo[(size_t)QKVN * H_SZ];

// ---------------------------------------------------------------------------
// fp32 -> (hi, lo) bf16 split:  x ~= hi + lo, |x - hi - lo| ~ 2^-18 |x|
// ---------------------------------------------------------------------------
__global__ __launch_bounds__(256) void cvt_split_kernel(
    const float* __restrict__ in,
    __nv_bfloat16* __restrict__ hi, __nv_bfloat16* __restrict__ lo, int n)
{
    int i = (blockIdx.x * 256 + threadIdx.x) * 4;
    if (i >= n) return;
    float4 v = *(const float4*)(in + i);
    __nv_bfloat16 h0 = __float2bfloat16_rn(v.x);
    __nv_bfloat16 h1 = __float2bfloat16_rn(v.y);
    __nv_bfloat16 h2 = __float2bfloat16_rn(v.z);
    __nv_bfloat16 h3 = __float2bfloat16_rn(v.w);
    __nv_bfloat16 l0 = __float2bfloat16_rn(v.x - __bfloat162float(h0));
    __nv_bfloat16 l1 = __float2bfloat16_rn(v.y - __bfloat162float(h1));
    __nv_bfloat16 l2 = __float2bfloat16_rn(v.z - __bfloat162float(h2));
    __nv_bfloat16 l3 = __float2bfloat16_rn(v.w - __bfloat162float(h3));
    __nv_bfloat162 hA = {h0, h1}, hB = {h2, h3};
    __nv_bfloat162 lA = {l0, l1}, lB = {l2, l3};
    uint2 hu, lu;
    hu.x = *reinterpret_cast<uint32_t*>(&hA);
    hu.y = *reinterpret_cast<uint32_t*>(&hB);
    lu.x = *reinterpret_cast<uint32_t*>(&lA);
    lu.y = *reinterpret_cast<uint32_t*>(&lB);
    *reinterpret_cast<uint2*>(hi + i) = hu;
    *reinterpret_cast<uint2*>(lo + i) = lu;
}

// ---------------------------------------------------------------------------
// Split-bf16 tensor-core GEMM (NT): C[M,N] = (Ahi+Alo)[M,K] * (Bhi+Blo)[N,K]^T
// via 3 MMAs per tile: AhiBhi + AhiBlo + AloBhi, fp32 accum.
// Tile 128x128, BK=32, 256 threads = 8 warps in 2(M) x 4(N); warp = 64x32.
// cp.async 2-stage pipeline; smem rows padded to 40 halves (80B) so both the
// 16B cp.async chunks stay aligned and all fragment LDS are bank-conflict-free
// (row stride 20 words: 20r mod 32 hits 8 distinct groups of 4 banks).
// ---------------------------------------------------------------------------
#define GK        1024
#define BKG       32
#define KSTEPS    (GK / BKG)            // 32
#define ROWP      40                    // padded row length in bf16
#define PLANE_H   (128 * ROWP)          // halfwords per plane  = 5120
#define STAGE_H   (4 * PLANE_H)         // Ahi,Alo,Bhi,Blo      = 20480
#define GEMM_SMEM_BYTES (2 * STAGE_H * 2)  // 2 stages * halfwords * 2B = 81920

__device__ __forceinline__ void cp_async16(uint32_t saddr, const void* gptr) {
    asm volatile("cp.async.cg.shared.global [%0], [%1], 16;\n"
                 :: "r"(saddr), "l"(gptr) : "memory");
}
__device__ __forceinline__ void cp_commit() {
    asm volatile("cp.async.commit_group;\n" ::: "memory");
}
template <int N>
__device__ __forceinline__ void cp_wait() {
    asm volatile("cp.async.wait_group %0;\n" :: "n"(N) : "memory");
}
__device__ __forceinline__ void mma_bf16(float& d0, float& d1, float& d2, float& d3,
                                         uint32_t a0, uint32_t a1, uint32_t a2, uint32_t a3,
                                         uint32_t b0, uint32_t b1) {
    asm volatile(
        "mma.sync.aligned.m16n8k16.row.col.f32.bf16.bf16.f32 "
        "{%0,%1,%2,%3}, {%4,%5,%6,%7}, {%8,%9}, {%0,%1,%2,%3};\n"
        : "+f"(d0), "+f"(d1), "+f"(d2), "+f"(d3)
        : "r"(a0), "r"(a1), "r"(a2), "r"(a3), "r"(b0), "r"(b1));
}

__global__ __launch_bounds__(256) void gemm_bf16x3_128x128(
    const __nv_bfloat16* __restrict__ Ahi, const __nv_bfloat16* __restrict__ Alo,
    const __nv_bfloat16* __restrict__ Bhi, const __nv_bfloat16* __restrict__ Blo,
    const float* __restrict__ bias, float* __restrict__ C, int M, int N)
{
    extern __shared__ __nv_bfloat16 sm[];
    const uint32_t smem_u32 = (uint32_t)__cvta_generic_to_shared(sm);

    const int t  = threadIdx.x;
    const int m0 = blockIdx.y * 128;
    const int n0 = blockIdx.x * 128;
    const int wid = t >> 5, l = t & 31;
    const int wm = wid >> 2;            // 0..1  -> M offset wm*64
    const int wn = wid & 3;             // 0..3  -> N offset wn*32
    const int fr = l >> 2;              // fragment row/col within 8
    const int fc = (l & 3) * 2;         // fragment k halfword offset

    // cp.async chunk mapping: per plane 128 rows x 4 chunks(16B) = 512; 2/thread
    const int crow0 = t >> 2;           // chunk set 0: rows 0..63? no: id=t -> row=t/4
    // (we just recompute inside the lambda-style loader below)

    float acc[4][4][4];
#pragma unroll
    for (int a = 0; a < 4; a++)
#pragma unroll
        for (int b = 0; b < 4; b++)
#pragma unroll
            for (int c = 0; c < 4; c++) acc[a][b][c] = 0.f;

    // ---- stage loader ----
    auto load_stage = [&](int stage, int k0) {
        const uint32_t sbase = smem_u32 + (uint32_t)stage * STAGE_H * 2; // bytes
#pragma unroll
        for (int j = 0; j < 2; j++) {
            int id  = t + 256 * j;
            int row = id >> 2, ch = (id & 3) * 8;           // ch in elements
            // A planes
            const __nv_bfloat16* ga_h = Ahi + (size_t)(m0 + row) * GK + k0 + ch;
            const __nv_bfloat16* ga_l = Alo + (size_t)(m0 + row) * GK + k0 + ch;
            uint32_t sa = sbase + (uint32_t)(row * ROWP + ch) * 2;
            cp_async16(sa,                 ga_h);
            cp_async16(sa + PLANE_H * 2,   ga_l);
            // B planes
            const __nv_bfloat16* gb_h = Bhi + (size_t)(n0 + row) * GK + k0 + ch;
            const __nv_bfloat16* gb_l = Blo + (size_t)(n0 + row) * GK + k0 + ch;
            cp_async16(sa + PLANE_H * 4,   gb_h);
            cp_async16(sa + PLANE_H * 6,   gb_l);
        }
    };

    load_stage(0, 0);
    cp_commit();

    for (int ks = 0; ks < KSTEPS; ks++) {
        const bool more = (ks + 1 < KSTEPS);
        if (more) { load_stage((ks + 1) & 1, (ks + 1) * BKG); cp_commit(); }
        if (more) cp_wait<1>(); else cp_wait<0>();
        __syncthreads();

        const __nv_bfloat16* sA_hi = sm + (size_t)(ks & 1) * STAGE_H;
        const __nv_bfloat16* sA_lo = sA_hi + PLANE_H;
        const __nv_bfloat16* sB_hi = sA_hi + 2 * PLANE_H;
        const __nv_bfloat16* sB_lo = sA_hi + 3 * PLANE_H;

#pragma unroll
        for (int kk = 0; kk < BKG; kk += 16) {
            // Load all A fragments (hi & lo) for this k16
            uint32_t ahi[4][4], alo[4][4];
#pragma unroll
            for (int mi = 0; mi < 4; mi++) {
                int rb = wm * 64 + mi * 16;
                int i0 = (rb + fr) * ROWP + kk + fc;
                ahi[mi][0] = *(const uint32_t*)&sA_hi[i0];
                ahi[mi][1] = *(const uint32_t*)&sA_hi[i0 + 8 * ROWP];
                ahi[mi][2] = *(const uint32_t*)&sA_hi[i0 + 8];
                ahi[mi][3] = *(const uint32_t*)&sA_hi[i0 + 8 * ROWP + 8];
                alo[mi][0] = *(const uint32_t*)&sA_lo[i0];
                alo[mi][1] = *(const uint32_t*)&sA_lo[i0 + 8 * ROWP];
                alo[mi][2] = *(const uint32_t*)&sA_lo[i0 + 8];
                alo[mi][3] = *(const uint32_t*)&sA_lo[i0 + 8 * ROWP + 8];
            }
#pragma unroll
            for (int nj = 0; nj < 4; nj++) {
                int cb = wn * 32 + nj * 8;
                int i0 = (cb + fr) * ROWP + kk + fc;
                uint32_t bh0 = *(const uint32_t*)&sB_hi[i0];
                uint32_t bh1 = *(const uint32_t*)&sB_hi[i0 + 8];
                uint32_t bl0 = *(const uint32_t*)&sB_lo[i0];
                uint32_t bl1 = *(const uint32_t*)&sB_lo[i0 + 8];
#pragma unroll
                for (int mi = 0; mi < 4; mi++) {
                    float* d = acc[mi][nj];
                    mma_bf16(d[0], d[1], d[2], d[3],
                             ahi[mi][0], ahi[mi][1], ahi[mi][2], ahi[mi][3], bh0, bh1);
                    mma_bf16(d[0], d[1], d[2], d[3],
                             ahi[mi][0], ahi[mi][1], ahi[mi][2], ahi[mi][3], bl0, bl1);
                    mma_bf16(d[0], d[1], d[2], d[3],
                             alo[mi][0], alo[mi][1], alo[mi][2], alo[mi][3], bh0, bh1);
                }
            }
        }
        __syncthreads();
    }

    // Epilogue: C-fragment mapping c0,c1 -> (row fr, col 2(l&3)+{0,1}),
    // c2,c3 -> row fr+8.
#pragma unroll
    for (int mi = 0; mi < 4; mi++) {
#pragma unroll
        for (int nj = 0; nj < 4; nj++) {
            int row = m0 + wm * 64 + mi * 16 + fr;
            int col = n0 + wn * 32 + nj * 8 + (l & 3) * 2;
            float b0 = 0.f, b1 = 0.f;
            if (bias != nullptr) { b0 = bias[col]; b1 = bias[col + 1]; }
            float2 v0 = make_float2(acc[mi][nj][0] + b0, acc[mi][nj][1] + b1);
            float2 v1 = make_float2(acc[mi][nj][2] + b0, acc[mi][nj][3] + b1);
            *(float2*)&C[(size_t)row * N + col]       = v0;
            *(float2*)&C[(size_t)(row + 8) * N + col] = v1;
        }
    }
}

// ---------------------------------------------------------------------------
// Flash attention: one CTA = (64 q-rows) x (one b,h). Streams 16 k-tiles of 64.
// (unchanged from the verified R7 kernel)
// ---------------------------------------------------------------------------
#define ATTN_SMEM_FLOATS (64*68 + 64*68 + 64*64 + 64*65 + 3*64)
#define ATTN_SMEM_BYTES  (ATTN_SMEM_FLOATS * 4)

__global__ __launch_bounds__(256) void attn_flash_kernel(
    const float* __restrict__ qkv, float* __restrict__ o)
{
    extern __shared__ float smf[];
    float* Qt    = smf;                // [64 d][68]  Qt[d*68 + x], pre-scaled
    float* Kt    = Qt + 64 * 68;       // [64 d][68]  Kt[d*68 + y]
    float* Vs    = Kt + 64 * 68;       // [64 y][64]  Vs[y*64 + d]
    float* Ss    = Vs + 64 * 64;       // [64 r][65]  scores -> probs
    float* row_m = Ss + 64 * 65;       // [64]
    float* row_l = row_m + 64;         // [64]
    float* row_c = row_l + 64;         // [64] correction factor

    const int t  = threadIdx.x;
    const int qb = blockIdx.x;         // 0..15 q-tile
    const int bh = blockIdx.y;         // 0..127
    const int b  = bh >> 4;
    const int h  = bh & 15;
    const int x0 = qb * 64;

    const float* qbase = qkv + ((size_t)(b * L_SZ + x0)) * QKVN + h * HD_SZ;
    const float* kbase = qkv + (size_t)b * L_SZ * QKVN + H_SZ + h * HD_SZ;
    const float* vbase = kbase + H_SZ;
    const float scale = 0.125f;        // 1/sqrt(64)

#pragma unroll
    for (int i = 0; i < 16; i++) {
        int idx = t + 256 * i;
        int x = idx >> 6, d = idx & 63;
        Qt[d * 68 + x] = qbase[(size_t)x * QKVN + d] * scale;
    }
    if (t < 64) { row_m[t] = -CUDART_INF_F; row_l[t] = 0.f; }

    const int r0 = (t >> 4) * 4;       // q-row group
    const int c0 = (t & 15) * 4;       // k-col / out-col group
    float acc[4][4];
#pragma unroll
    for (int i = 0; i < 4; i++)
#pragma unroll
        for (int j = 0; j < 4; j++) acc[i][j] = 0.f;

    for (int kt = 0; kt < 16; kt++) {
        const float* kp = kbase + (size_t)kt * 64 * QKVN;
        const float* vp = vbase + (size_t)kt * 64 * QKVN;
        __syncthreads();
#pragma unroll
        for (int i = 0; i < 16; i++) {
            int idx = t + 256 * i;
            int y = idx >> 6, d = idx & 63;
            Kt[d * 68 + y] = kp[(size_t)y * QKVN + d];
            Vs[y * 64 + d] = vp[(size_t)y * QKVN + d];
        }
        __syncthreads();

        float s[4][4];
#pragma unroll
        for (int i = 0; i < 4; i++)
#pragma unroll
            for (int j = 0; j < 4; j++) s[i][j] = 0.f;
#pragma unroll 16
        for (int d = 0; d < 64; d++) {
            float4 qa = *(const float4*)&Qt[d * 68 + r0];
            float4 kb = *(const float4*)&Kt[d * 68 + c0];
            s[0][0] = fmaf(qa.x, kb.x, s[0][0]); s[0][1] = fmaf(qa.x, kb.y, s[0][1]);
            s[0][2] = fmaf(qa.x, kb.z, s[0][2]); s[0][3] = fmaf(qa.x, kb.w, s[0][3]);
            s[1][0] = fmaf(qa.y, kb.x, s[1][0]); s[1][1] = fmaf(qa.y, kb.y, s[1][1]);
            s[1][2] = fmaf(qa.y, kb.z, s[1][2]); s[1][3] = fmaf(qa.y, kb.w, s[1][3]);
            s[2][0] = fmaf(qa.z, kb.x, s[2][0]); s[2][1] = fmaf(qa.z, kb.y, s[2][1]);
            s[2][2] = fmaf(qa.z, kb.z, s[2][2]); s[2][3] = fmaf(qa.z, kb.w, s[2][3]);
            s[3][0] = fmaf(qa.w, kb.x, s[3][0]); s[3][1] = fmaf(qa.w, kb.y, s[3][1]);
            s[3][2] = fmaf(qa.w, kb.z, s[3][2]); s[3][3] = fmaf(qa.w, kb.w, s[3][3]);
        }
#pragma unroll
        for (int i = 0; i < 4; i++)
#pragma unroll
            for (int j = 0; j < 4; j++)
                Ss[(r0 + i) * 65 + c0 + j] = s[i][j];
        __syncthreads();

        {
            const int r = t >> 2, seg = t & 3;
            float mx = -CUDART_INF_F;
#pragma unroll
            for (int j = 0; j < 16; j++)
                mx = fmaxf(mx, Ss[r * 65 + seg * 16 + j]);
            mx = fmaxf(mx, __shfl_xor_sync(0xffffffffu, mx, 1));
            mx = fmaxf(mx, __shfl_xor_sync(0xffffffffu, mx, 2));
            float m_old = row_m[r];
            float m_new = fmaxf(m_old, mx);
            float sum = 0.f;
#pragma unroll
            for (int j = 0; j < 16; j++) {
                float p = __expf(Ss[r * 65 + seg * 16 + j] - m_new);
                Ss[r * 65 + seg * 16 + j] = p;
                sum += p;
            }
            sum += __shfl_xor_sync(0xffffffffu, sum, 1);
            sum += __shfl_xor_sync(0xffffffffu, sum, 2);
            if (seg == 0) {
                row_c[r] = __expf(m_old - m_new);
                row_l[r] = row_l[r] * row_c[r] + sum;
                row_m[r] = m_new;
            }
        }
        __syncthreads();

        float cr[4];
#pragma unroll
        for (int i = 0; i < 4; i++) cr[i] = row_c[r0 + i];
#pragma unroll
        for (int i = 0; i < 4; i++)
#pragma unroll
            for (int j = 0; j < 4; j++) acc[i][j] *= cr[i];
#pragma unroll 16
        for (int y = 0; y < 64; y++) {
            float4 v = *(const float4*)&Vs[y * 64 + c0];
            float p0 = Ss[(r0 + 0) * 65 + y];
            float p1 = Ss[(r0 + 1) * 65 + y];
            float p2 = Ss[(r0 + 2) * 65 + y];
            float p3 = Ss[(r0 + 3) * 65 + y];
            acc[0][0] = fmaf(p0, v.x, acc[0][0]); acc[0][1] = fmaf(p0, v.y, acc[0][1]);
            acc[0][2] = fmaf(p0, v.z, acc[0][2]); acc[0][3] = fmaf(p0, v.w, acc[0][3]);
            acc[1][0] = fmaf(p1, v.x, acc[1][0]); acc[1][1] = fmaf(p1, v.y, acc[1][1]);
            acc[1][2] = fmaf(p1, v.z, acc[1][2]); acc[1][3] = fmaf(p1, v.w, acc[1][3]);
            acc[2][0] = fmaf(p2, v.x, acc[2][0]); acc[2][1] = fmaf(p2, v.y, acc[2][1]);
            acc[2][2] = fmaf(p2, v.z, acc[2][2]); acc[2][3] = fmaf(p2, v.w, acc[2][3]);
            acc[3][0] = fmaf(p3, v.x, acc[3][0]); acc[3][1] = fmaf(p3, v.y, acc[3][1]);
            acc[3][2] = fmaf(p3, v.z, acc[3][2]); acc[3][3] = fmaf(p3, v.w, acc[3][3]);
        }
    }

#pragma unroll
    for (int i = 0; i < 4; i++) {
        float inv = 1.0f / row_l[r0 + i];
        float4 v = make_float4(acc[i][0] * inv, acc[i][1] * inv,
                               acc[i][2] * inv, acc[i][3] * inv);
        *(float4*)&o[((size_t)(b * L_SZ + x0 + r0 + i)) * H_SZ + h * HD_SZ + c0] = v;
    }
}

// ---------------------------------------------------------------------------
extern "C" void kernel_launch(void* const* d_in, const int* in_sizes, int n_in,
                              void* d_out, int out_size)
{
    const float* x     = (const float*)d_in[0];
    const float* w_qkv = (const float*)d_in[1];
    const float* w_out = (const float*)d_in[2];
    const float* b_out = (const float*)d_in[3];
    float* out = (float*)d_out;

    float *qkv = nullptr, *ob = nullptr;
    __nv_bfloat16 *Ahi = nullptr, *Alo = nullptr, *Bhi = nullptr, *Blo = nullptr;
    cudaGetSymbolAddress((void**)&qkv, g_qkv);
    cudaGetSymbolAddress((void**)&ob,  g_o);
    cudaGetSymbolAddress((void**)&Ahi, g_Ahi);
    cudaGetSymbolAddress((void**)&Alo, g_Alo);
    cudaGetSymbolAddress((void**)&Bhi, g_Bhi);
    cudaGetSymbolAddress((void**)&Blo, g_Blo);

    cudaFuncSetAttribute(attn_flash_kernel,
                         cudaFuncAttributeMaxDynamicSharedMemorySize,
                         ATTN_SMEM_BYTES);
    cudaFuncSetAttribute(gemm_bf16x3_128x128,
                         cudaFuncAttributeMaxDynamicSharedMemorySize,
                         GEMM_SMEM_BYTES);

    const int NX  = ML * H_SZ;        // 8.39M
    const int NWQ = QKVN * H_SZ;      // 3.15M
    const int NWO = H_SZ * H_SZ;      // 1.05M

    // 1) split x and w_qkv to bf16 hi/lo planes
    cvt_split_kernel<<<NX  / (256 * 4), 256>>>(x,     Ahi, Alo, NX);
    cvt_split_kernel<<<NWQ / (256 * 4), 256>>>(w_qkv, Bhi, Blo, NWQ);

    // 2) QKV projection (tensor cores): g_qkv = x @ w_qkv^T
    gemm_bf16x3_128x128<<<dim3(QKVN / 128, ML / 128), 256, GEMM_SMEM_BYTES>>>(
        Ahi, Alo, Bhi, Blo, nullptr, qkv, ML, QKVN);

    // 3) Attention -> g_o[8192, 1024] ([B, L, H] layout)
    attn_flash_kernel<<<dim3(L_SZ / 64, B_SZ * NH_SZ), 256, ATTN_SMEM_BYTES>>>(
        qkv, ob);

    // 4) split o and w_out (reuse planes)
    cvt_split_kernel<<<NX  / (256 * 4), 256>>>(ob,    Ahi, Alo, NX);
    cvt_split_kernel<<<NWO / (256 * 4), 256>>>(w_out, Bhi, Blo, NWO);

    // 5) Output projection + bias (tensor cores)
    gemm_bf16x3_128x128<<<dim3(H_SZ / 128, ML / 128), 256, GEMM_SMEM_BYTES>>>(
        Ahi, Alo, Bhi, Blo, b_out, out, ML, H_SZ);
}